// round 11
// baseline (speedup 1.0000x reference)
#include <cuda_runtime.h>
#include <math_constants.h>

// Problem constants
#define L_OBS   512
#define NSEG    8192
#define BPOSE   8
#define NRAY    (BPOSE * L_OBS)          // 4096
#define FOV_F   6.283185307179586
#define EPS_PAR 0.0001f

// Distance culling radius (map units). Any segment giving a valid hit at
// u <= RCUT has dist(pose, segment) <= RCUT (r is unit), so the culled set is
// exact for all beams that resolve with u <= RCUT. Beams that don't resolve
// within RCUT take the exact full-scan fallback below.
#define RCUT    8.0f
#define R2M     (RCUT * RCUT * 1.0012f)   // conservative margin >> fp32 slop

#define TPB     256                       // 8 warps: warp = list slice, lane = beam
#define NGRP    16                        // beam groups per pose (32 beams each)
#define CAP     2048                      // smem list capacity (overflow -> full scan)

__global__ __launch_bounds__(TPB)
void raycast_kernel(const float4* __restrict__ seg, const float* __restrict__ pose,
                    float* __restrict__ out)
{
    const int pz   = blockIdx.x >> 4;            // pose
    const int grp  = blockIdx.x & (NGRP - 1);    // 32-beam group
    const int tid  = threadIdx.x;
    const int wid  = tid >> 5;                   // list slice
    const int lane = tid & 31;                   // beam within group

    __shared__ float4 s_pk[CAP];    // (sx, sy, dx, dy)
    __shared__ float  s_na[CAP];    // num_a
    __shared__ int    s_cnt;
    __shared__ float  s_rn[8][32];
    __shared__ float  s_ra[8][32];

    if (tid == 0) s_cnt = 0;

    const float px = pose[pz * 3 + 0];
    const float py = pose[pz * 3 + 1];
    const float th = pose[pz * 3 + 2];
    __syncthreads();

    // ---- phase A: distance-cull ALL segments, compact survivors into smem
    for (int i = tid; i < NSEG; i += TPB) {
        float4 q = seg[i];
        float sx = q.z - q.x;
        float sy = q.w - q.y;
        float dx = px - q.x;      // AP = P - A
        float dy = py - q.y;

        // point-to-segment squared distance <= R2M, division-free
        float c    = dx * sx + dy * sy;          // dot(AP, S)
        float s2   = sx * sx + sy * sy;          // |S|^2
        float apsq = dx * dx + dy * dy;
        float bx = dx - sx, by = dy - sy;        // BP = P - B
        float bpsq = bx * bx + by * by;
        bool pass;
        if (c <= 0.0f)      pass = apsq <= R2M;
        else if (c >= s2)   pass = bpsq <= R2M;
        else                pass = (apsq * s2 - c * c) <= R2M * s2;

        unsigned m = __ballot_sync(0xffffffffu, pass);
        if (m) {
            int leader = __ffs(m) - 1;
            int base = 0;
            if (lane == leader) base = atomicAdd(&s_cnt, __popc(m));
            base = __shfl_sync(0xffffffffu, base, leader);
            if (pass) {
                int p = base + __popc(m & ((1u << lane) - 1u));
                if (p < CAP) {                   // overflow -> full-scan path
                    s_pk[p] = make_float4(sx, sy, dx, dy);
                    s_na[p] = sx * dy - sy * dx; // num_a (reference formula)
                }
            }
        }
    }
    __syncthreads();

    const int  cnt  = s_cnt;
    const bool over = cnt > CAP;                 // list incomplete (adversarial)
    const int  m2   = over ? 0 : cnt;

    const float kstep = (float)(FOV_F / (double)L_OBS);
    const int   beam  = grp * 32 + lane;
    const float ang   = (float)beam * kstep + th;
    const float rx = cosf(ang);
    const float ry = sinf(ang);

    // ---- phase B: exact test; warp w scans slice w (broadcast LDS per warp)
    float best_na = CUDART_INF_F;
    float best_a  = 1.0f;

    #pragma unroll 2
    for (int j = wid; j < m2; j += 8) {
        float4 p  = s_pk[j];
        float nai = s_na[j];
        float nb  = rx * p.w - ry * p.z;     // num_b
        float rxs = p.y * rx - p.x * ry;
        float absa  = fabsf(rxs);
        float absna = fabsf(nai);
        // valid <=> |rxs|>=eps, u_b = nb/rxs in [0,1], u_a = nai/rxs >= 0
        bool valid = (absa >= EPS_PAR) & (nb * rxs >= 0.0f)
                   & (fabsf(nb) <= absa) & (nai * rxs >= 0.0f);
        // cand u = absna/absa beats best iff absna*best_a < best_na*absa
        if (valid && (absna * best_a < best_na * absa)) {
            best_na = absna;
            best_a  = absa;
        }
    }

    // overflow path: exact scan of the whole segment array (never on this data)
    if (over) {
        for (int j = wid; j < NSEG; j += 8) {
            float4 q = __ldg(&seg[j]);
            float sx = q.z - q.x;
            float sy = q.w - q.y;
            float dx = px - q.x;
            float dy = py - q.y;
            float nai = sx * dy - sy * dx;
            float nb  = rx * dy - ry * dx;
            float rxs = sy * rx - sx * ry;
            float absa  = fabsf(rxs);
            float absna = fabsf(nai);
            bool valid = (absa >= EPS_PAR) & (nb * rxs >= 0.0f)
                       & (fabsf(nb) <= absa) & (nai * rxs >= 0.0f);
            if (valid && (absna * best_a < best_na * absa)) {
                best_na = absna; best_a = absa;
            }
        }
    }

    // ---- reduce the 8 slices per beam, warp 0 finishes
    s_rn[wid][lane] = best_na;
    s_ra[wid][lane] = best_a;
    __syncthreads();
    if (wid != 0) return;

    float bn = s_rn[0][lane];
    float ba = s_ra[0][lane];
    #pragma unroll
    for (int w = 1; w < 8; ++w) {
        float n2 = s_rn[w][lane];
        float a2 = s_ra[w][lane];
        if (n2 * ba < bn * a2) { bn = n2; ba = a2; }
    }
    float u = bn / ba;                            // inf if nothing valid

    // Resolved iff u <= RCUT (any better segment would have dist <= u <= RCUT
    // and thus be in the culled set). Overflow path already scanned everything.
    bool need_full = (!over) && !(u <= RCUT);
    if (__any_sync(0xffffffffu, need_full)) {
        float fn = CUDART_INF_F, fa = 1.0f;
        for (int j = 0; j < NSEG; ++j) {
            float4 q = __ldg(&seg[j]);
            float sx = q.z - q.x;
            float sy = q.w - q.y;
            float dx = px - q.x;
            float dy = py - q.y;
            float nai = sx * dy - sy * dx;
            float nb  = rx * dy - ry * dx;
            float rxs = sy * rx - sx * ry;
            float absa  = fabsf(rxs);
            float absna = fabsf(nai);
            bool valid = (absa >= EPS_PAR) & (nb * rxs >= 0.0f)
                       & (fabsf(nb) <= absa) & (nai * rxs >= 0.0f);
            if (valid && (absna * fa < fn * absa)) { fn = absna; fa = absa; }
        }
        if (need_full) u = fn / fa;
    }

    if (__any_sync(0xffffffffu, isinf(u))) {
        // Reference: argmin over all-inf returns idx 0 -> u_a[0] (parallel -> 0)
        float4 q = __ldg(&seg[0]);
        float sx = q.z - q.x;
        float sy = q.w - q.y;
        float dx = px - q.x;
        float dy = py - q.y;
        float num_a = sx * dy - sy * dx;
        float rxs   = sy * rx - sx * ry;
        float ufb = (fabsf(rxs) < EPS_PAR) ? 0.0f : (num_a / rxs);
        if (isinf(u)) u = ufb;
    }

    const float ix = px + rx * u;
    const float iy = py + ry * u;

    const int ray = pz * L_OBS + beam;
    const int gi  = ray * 2;
    out[gi + 0] = ix;
    out[gi + 1] = iy;

    const float c = cosf(th);
    const float s = sinf(th);
    const float ddx = ix - px;
    const float ddy = iy - py;
    out[NRAY * 2 + gi + 0] =  ddx * c + ddy * s;
    out[NRAY * 2 + gi + 1] = -ddx * s + ddy * c;
}

extern "C" void kernel_launch(void* const* d_in, const int* in_sizes, int n_in,
                              void* d_out, int out_size)
{
    const float4* seg  = (const float4*)d_in[0];   // line_seg [8192, 4]
    const float*  pose = (const float*)d_in[1];    // pose [8, 3]
    float* out = (float*)d_out;

    raycast_kernel<<<BPOSE * NGRP, TPB>>>(seg, pose, out);
}

// round 12
// speedup vs baseline: 1.7407x; 1.7407x over previous
#include <cuda_runtime.h>
#include <math_constants.h>

// Problem constants
#define L_OBS   512
#define NSEG    8192
#define BPOSE   8
#define NRAY    (BPOSE * L_OBS)          // 4096
#define FOV_F   6.283185307179586
#define EPS_PAR 0.0001f

// Distance culling radius (map units). Any segment giving a valid hit at
// u <= RCUT has dist(pose, segment) <= RCUT (r is unit), so the culled set is
// exact for all beams that resolve with u <= RCUT. Beams that don't resolve
// within RCUT take the exact full-scan fallback below.
#define RCUT    8.0f
#define R2M     (RCUT * RCUT * 1.0012f)   // conservative margin >> fp32 slop

#define TPB     512                       // 16 warps
#define NW      16                        // warps per block == list slices
#define SPW     (NSEG / NW)               // 512 segs culled per warp
#define NGRP    16                        // 32-beam groups per pose
#define CAPW    64                        // per-warp region capacity (mean ~18)

__global__ __launch_bounds__(TPB)
void raycast_kernel(const float4* __restrict__ seg, const float* __restrict__ pose,
                    float* __restrict__ out)
{
    const int pz   = blockIdx.x >> 4;            // pose
    const int grp  = blockIdx.x & (NGRP - 1);    // 32-beam group
    const int tid  = threadIdx.x;
    const int wid  = tid >> 5;                   // warp == cull span == slice
    const int lane = tid & 31;                   // beam within group

    __shared__ float4 s_pk[NW * CAPW];   // (sx, sy, dx, dy) per warp region
    __shared__ float  s_na[NW * CAPW];   // num_a
    __shared__ int    s_wcnt[NW];
    __shared__ int    s_over;
    __shared__ float  s_rn[NW][32];
    __shared__ float  s_ra[NW][32];

    if (tid == 0) s_over = 0;

    const float px = pose[pz * 3 + 0];
    const float py = pose[pz * 3 + 1];
    const float th = pose[pz * 3 + 2];

    // ---- phase A: warp-private distance cull + compaction (NO atomics)
    {
        int cnt = 0;
        const unsigned ltmask = (1u << lane) - 1u;
        #pragma unroll 4
        for (int i = 0; i < SPW / 32; ++i) {
            float4 q = seg[wid * SPW + i * 32 + lane];
            float sx = q.z - q.x;
            float sy = q.w - q.y;
            float dx = px - q.x;      // AP = P - A
            float dy = py - q.y;

            // point-to-segment squared distance <= R2M, division-free
            float c    = dx * sx + dy * sy;          // dot(AP, S)
            float s2   = sx * sx + sy * sy;          // |S|^2
            float apsq = dx * dx + dy * dy;
            float bx = dx - sx, by = dy - sy;        // BP = P - B
            float bpsq = bx * bx + by * by;
            bool pass;
            if (c <= 0.0f)      pass = apsq <= R2M;
            else if (c >= s2)   pass = bpsq <= R2M;
            else                pass = (apsq * s2 - c * c) <= R2M * s2;

            unsigned m = __ballot_sync(0xffffffffu, pass);
            if (pass) {
                int p = cnt + __popc(m & ltmask);
                if (p < CAPW) {
                    s_pk[wid * CAPW + p] = make_float4(sx, sy, dx, dy);
                    s_na[wid * CAPW + p] = sx * dy - sy * dx;  // num_a
                }
            }
            cnt += __popc(m);
        }
        if (lane == 0) {
            s_wcnt[wid] = (cnt > CAPW) ? CAPW : cnt;
            if (cnt > CAPW) s_over = 1;              // adversarial overflow
        }
    }
    __syncthreads();

    const float kstep = (float)(FOV_F / (double)L_OBS);
    const int   beam  = grp * 32 + lane;
    const float ang   = (float)beam * kstep + th;
    const float rx = cosf(ang);
    const float ry = sinf(ang);

    // ---- phase B: exact test; warp w scans its own region (broadcast LDS)
    float best_na = CUDART_INF_F;
    float best_a  = 1.0f;
    const int m2 = s_wcnt[wid];

    #pragma unroll 2
    for (int j = 0; j < m2; ++j) {
        float4 p  = s_pk[wid * CAPW + j];
        float nai = s_na[wid * CAPW + j];
        float nb  = rx * p.w - ry * p.z;     // num_b
        float rxs = p.y * rx - p.x * ry;
        float absa  = fabsf(rxs);
        float absna = fabsf(nai);
        // valid <=> |rxs|>=eps, u_b = nb/rxs in [0,1], u_a = nai/rxs >= 0
        bool valid = (absa >= EPS_PAR) & (nb * rxs >= 0.0f)
                   & (fabsf(nb) <= absa) & (nai * rxs >= 0.0f);
        // cand u = absna/absa beats best iff absna*best_a < best_na*absa
        if (valid && (absna * best_a < best_na * absa)) {
            best_na = absna;
            best_a  = absa;
        }
    }

    // ---- reduce the 16 slices per beam, warp 0 finishes the block's 32 beams
    s_rn[wid][lane] = best_na;
    s_ra[wid][lane] = best_a;
    __syncthreads();
    if (wid != 0) return;

    float bn = s_rn[0][lane];
    float ba = s_ra[0][lane];
    #pragma unroll
    for (int w = 1; w < NW; ++w) {
        float n2 = s_rn[w][lane];
        float a2 = s_ra[w][lane];
        if (n2 * ba < bn * a2) { bn = n2; ba = a2; }
    }
    float u = bn / ba;                            // inf if nothing valid

    // Resolved iff u <= RCUT (any closer segment would have dist <= u <= RCUT
    // and thus be in the culled set). Overflowed lists force the full scan.
    bool need_full = s_over || !(u <= RCUT);
    if (__any_sync(0xffffffffu, need_full)) {
        float fn = CUDART_INF_F, fa = 1.0f;
        for (int j = 0; j < NSEG; ++j) {
            float4 q = __ldg(&seg[j]);
            float sx = q.z - q.x;
            float sy = q.w - q.y;
            float dx = px - q.x;
            float dy = py - q.y;
            float nai = sx * dy - sy * dx;
            float nb  = rx * dy - ry * dx;
            float rxs = sy * rx - sx * ry;
            float absa  = fabsf(rxs);
            float absna = fabsf(nai);
            bool valid = (absa >= EPS_PAR) & (nb * rxs >= 0.0f)
                       & (fabsf(nb) <= absa) & (nai * rxs >= 0.0f);
            if (valid && (absna * fa < fn * absa)) { fn = absna; fa = absa; }
        }
        if (need_full) u = fn / fa;
    }

    if (__any_sync(0xffffffffu, isinf(u))) {
        // Reference: argmin over all-inf returns idx 0 -> u_a[0] (parallel -> 0)
        float4 q = __ldg(&seg[0]);
        float sx = q.z - q.x;
        float sy = q.w - q.y;
        float dx = px - q.x;
        float dy = py - q.y;
        float num_a = sx * dy - sy * dx;
        float rxs   = sy * rx - sx * ry;
        float ufb = (fabsf(rxs) < EPS_PAR) ? 0.0f : (num_a / rxs);
        if (isinf(u)) u = ufb;
    }

    const float ix = px + rx * u;
    const float iy = py + ry * u;

    const int ray = pz * L_OBS + beam;
    const int gi  = ray * 2;
    out[gi + 0] = ix;
    out[gi + 1] = iy;

    const float c = cosf(th);
    const float s = sinf(th);
    const float ddx = ix - px;
    const float ddy = iy - py;
    out[NRAY * 2 + gi + 0] =  ddx * c + ddy * s;
    out[NRAY * 2 + gi + 1] = -ddx * s + ddy * c;
}

extern "C" void kernel_launch(void* const* d_in, const int* in_sizes, int n_in,
                              void* d_out, int out_size)
{
    const float4* seg  = (const float4*)d_in[0];   // line_seg [8192, 4]
    const float*  pose = (const float*)d_in[1];    // pose [8, 3]
    float* out = (float*)d_out;

    raycast_kernel<<<BPOSE * NGRP, TPB>>>(seg, pose, out);
}

// round 13
// speedup vs baseline: 1.8359x; 1.0547x over previous
#include <cuda_runtime.h>
#include <math_constants.h>

// Problem constants
#define L_OBS   512
#define NSEG    8192
#define BPOSE   8
#define NRAY    (BPOSE * L_OBS)          // 4096
#define FOV_F   6.283185307179586
#define EPS_PAR 0.0001f

// Distance culling radius (map units). Any segment giving a valid hit at
// u <= RCUT has dist(pose, segment) <= RCUT (r is unit), so the culled set is
// exact for all beams that resolve with u <= RCUT. Beams that don't resolve
// within RCUT take the exact full-scan fallback below.
#define RCUT    8.0f
#define R2M     (RCUT * RCUT * 1.0012f)   // conservative margin >> fp32 slop

#define TPB     512                       // 16 warps
#define NW      16
#define NCH     16                        // chunk-blocks per pose (512 segs each)
#define CAP     1024                      // smem list capacity (list fits if <= CAP)

// Per-pose shared list in global memory (capacity NSEG -> can never overflow).
__device__ float4 g_lpk[BPOSE * NSEG];
__device__ float  g_lna[BPOSE * NSEG];
__device__ int    g_cnt[BPOSE];           // list size     (reset by last reader)
__device__ int    g_ready[BPOSE];         // builder arrivals (reset by last reader)
__device__ int    g_fin[BPOSE];           // reader arrivals  (reset by last reader)

__global__ __launch_bounds__(TPB)
void raycast_kernel(const float4* __restrict__ seg, const float* __restrict__ pose,
                    float* __restrict__ out)
{
    const int pz    = blockIdx.x >> 4;           // pose
    const int chunk = blockIdx.x & (NCH - 1);    // segment chunk == beam group
    const int tid   = threadIdx.x;
    const int wid   = tid >> 5;
    const int lane  = tid & 31;

    __shared__ float4 s_pk[CAP];
    __shared__ float  s_na[CAP];
    __shared__ int    s_cnt, s_base, s_total;
    __shared__ float  s_rn[NW][32];
    __shared__ float  s_ra[NW][32];

    if (tid == 0) s_cnt = 0;

    const float px = pose[pz * 3 + 0];
    const float py = pose[pz * 3 + 1];
    const float th = pose[pz * 3 + 2];
    __syncthreads();

    // ---- build: cull this block's 512 segments (1 per thread), compact in smem
    {
        float4 q = seg[chunk * TPB + tid];
        float sx = q.z - q.x;
        float sy = q.w - q.y;
        float dx = px - q.x;      // AP = P - A
        float dy = py - q.y;

        // point-to-segment squared distance <= R2M, division-free
        float c    = dx * sx + dy * sy;          // dot(AP, S)
        float s2   = sx * sx + sy * sy;          // |S|^2
        float apsq = dx * dx + dy * dy;
        float bx = dx - sx, by = dy - sy;        // BP = P - B
        float bpsq = bx * bx + by * by;
        bool pass;
        if (c <= 0.0f)      pass = apsq <= R2M;
        else if (c >= s2)   pass = bpsq <= R2M;
        else                pass = (apsq * s2 - c * c) <= R2M * s2;

        unsigned m = __ballot_sync(0xffffffffu, pass);
        if (m) {
            int leader = __ffs(m) - 1;
            int base = 0;
            if (lane == leader) base = atomicAdd(&s_cnt, __popc(m));
            base = __shfl_sync(0xffffffffu, base, leader);
            if (pass) {
                int p = base + __popc(m & ((1u << lane) - 1u));
                s_pk[p] = make_float4(sx, sy, dx, dy);   // p < 512 <= CAP always
                s_na[p] = sx * dy - sy * dx;             // num_a (reference)
            }
        }
    }
    __syncthreads();

    // ---- publish: one global atomic per block, coalesced copy smem -> global
    if (tid == 0) s_base = atomicAdd(&g_cnt[pz], s_cnt);
    __syncthreads();
    const int bcnt = s_cnt;
    const int base = s_base;
    for (int i = tid; i < bcnt; i += TPB) {
        g_lpk[pz * NSEG + base + i] = s_pk[i];
        g_lna[pz * NSEG + base + i] = s_na[i];
    }
    __threadfence();
    __syncthreads();

    // ---- barrier: arrive, then spin until all 16 builders of this pose arrived.
    // Grid (128 blocks) is a guaranteed single wave -> no deadlock.
    if (tid == 0) {
        atomicAdd(&g_ready[pz], 1);
        while (atomicAdd(&g_ready[pz], 0) < NCH) { }
        __threadfence();
        s_total = atomicAdd(&g_cnt[pz], 0);
        // reader arrival; last reader resets counters for the next launch/replay
        if (atomicAdd(&g_fin[pz], 1) == NCH - 1) {
            atomicExch(&g_cnt[pz], 0);
            atomicExch(&g_ready[pz], 0);
            atomicExch(&g_fin[pz], 0);
        }
    }
    __syncthreads();
    const int cnt = s_total;

    // ---- stage the full pose list into smem (typ ~290 entries)
    const bool insm = (cnt <= CAP);
    if (insm) {
        for (int i = tid; i < cnt; i += TPB) {
            s_pk[i] = g_lpk[pz * NSEG + i];
            s_na[i] = g_lna[pz * NSEG + i];
        }
    }
    __syncthreads();

    const float kstep = (float)(FOV_F / (double)L_OBS);
    const int   beam  = chunk * 32 + lane;       // block owns 32 beams
    const float ang   = (float)beam * kstep + th;
    const float rx = cosf(ang);
    const float ry = sinf(ang);

    // ---- phase B: exact test; warp w scans slice w (broadcast reads)
    float best_na = CUDART_INF_F;
    float best_a  = 1.0f;

    if (insm) {
        #pragma unroll 2
        for (int j = wid; j < cnt; j += NW) {
            float4 p  = s_pk[j];
            float nai = s_na[j];
            float nb  = rx * p.w - ry * p.z;     // num_b
            float rxs = p.y * rx - p.x * ry;
            float absa  = fabsf(rxs);
            float absna = fabsf(nai);
            bool valid = (absa >= EPS_PAR) & (nb * rxs >= 0.0f)
                       & (fabsf(nb) <= absa) & (nai * rxs >= 0.0f);
            if (valid && (absna * best_a < best_na * absa)) {
                best_na = absna;
                best_a  = absa;
            }
        }
    } else {                                     // huge list: read via L2
        for (int j = wid; j < cnt; j += NW) {
            float4 p  = g_lpk[pz * NSEG + j];
            float nai = g_lna[pz * NSEG + j];
            float nb  = rx * p.w - ry * p.z;
            float rxs = p.y * rx - p.x * ry;
            float absa  = fabsf(rxs);
            float absna = fabsf(nai);
            bool valid = (absa >= EPS_PAR) & (nb * rxs >= 0.0f)
                       & (fabsf(nb) <= absa) & (nai * rxs >= 0.0f);
            if (valid && (absna * best_a < best_na * absa)) {
                best_na = absna;
                best_a  = absa;
            }
        }
    }

    // ---- reduce 16 slices per beam; warp 0 finalizes the block's 32 beams
    s_rn[wid][lane] = best_na;
    s_ra[wid][lane] = best_a;
    __syncthreads();
    if (wid != 0) return;

    float bn = s_rn[0][lane];
    float ba = s_ra[0][lane];
    #pragma unroll
    for (int w = 1; w < NW; ++w) {
        float n2 = s_rn[w][lane];
        float a2 = s_ra[w][lane];
        if (n2 * ba < bn * a2) { bn = n2; ba = a2; }
    }
    float u = bn / ba;                            // inf if nothing valid

    // Resolved iff u <= RCUT (any closer segment would have dist <= u <= RCUT
    // and thus be in the list). Otherwise: exact full scan (reference semantics).
    bool need_full = !(u <= RCUT);
    if (__any_sync(0xffffffffu, need_full)) {
        float fn = CUDART_INF_F, fa = 1.0f;
        for (int j = 0; j < NSEG; ++j) {
            float4 q = __ldg(&seg[j]);
            float sx = q.z - q.x;
            float sy = q.w - q.y;
            float dx = px - q.x;
            float dy = py - q.y;
            float nai = sx * dy - sy * dx;
            float nb  = rx * dy - ry * dx;
            float rxs = sy * rx - sx * ry;
            float absa  = fabsf(rxs);
            float absna = fabsf(nai);
            bool valid = (absa >= EPS_PAR) & (nb * rxs >= 0.0f)
                       & (fabsf(nb) <= absa) & (nai * rxs >= 0.0f);
            if (valid && (absna * fa < fn * absa)) { fn = absna; fa = absa; }
        }
        if (need_full) u = fn / fa;
    }

    if (__any_sync(0xffffffffu, isinf(u))) {
        // Reference: argmin over all-inf returns idx 0 -> u_a[0] (parallel -> 0)
        float4 q = __ldg(&seg[0]);
        float sx = q.z - q.x;
        float sy = q.w - q.y;
        float dx = px - q.x;
        float dy = py - q.y;
        float num_a = sx * dy - sy * dx;
        float rxs   = sy * rx - sx * ry;
        float ufb = (fabsf(rxs) < EPS_PAR) ? 0.0f : (num_a / rxs);
        if (isinf(u)) u = ufb;
    }

    const float ix = px + rx * u;
    const float iy = py + ry * u;

    const int ray = pz * L_OBS + beam;
    const int gi  = ray * 2;
    out[gi + 0] = ix;
    out[gi + 1] = iy;

    const float c = cosf(th);
    const float s = sinf(th);
    const float ddx = ix - px;
    const float ddy = iy - py;
    out[NRAY * 2 + gi + 0] =  ddx * c + ddy * s;
    out[NRAY * 2 + gi + 1] = -ddx * s + ddy * c;
}

extern "C" void kernel_launch(void* const* d_in, const int* in_sizes, int n_in,
                              void* d_out, int out_size)
{
    const float4* seg  = (const float4*)d_in[0];   // line_seg [8192, 4]
    const float*  pose = (const float*)d_in[1];    // pose [8, 3]
    float* out = (float*)d_out;

    raycast_kernel<<<BPOSE * NCH, TPB>>>(seg, pose, out);
}

// round 15
// speedup vs baseline: 2.2240x; 1.2114x over previous
#include <cuda_runtime.h>
#include <math_constants.h>

// Problem constants
#define L_OBS   512
#define NSEG    8192
#define BPOSE   8
#define NRAY    (BPOSE * L_OBS)          // 4096
#define FOV_F   6.283185307179586
#define EPS_PAR 0.0001f

// Distance culling radius (map units). Any segment giving a valid hit at
// u <= RCUT has dist(pose, segment) <= RCUT (r is unit), so the culled set is
// exact for all beams that resolve with u <= RCUT. Beams that don't resolve
// within RCUT take the exact full-scan fallback below.
#define RCUT    8.0f
#define R2M     (RCUT * RCUT * 1.0012f)   // conservative margin >> fp32 slop

#define SCH     16                        // segment chunks per pose
#define CHSEG   (NSEG / SCH)              // 512 segs per chunk (1 per thread)
#define TPB     512                       // thread == beam

// Static scratch (zero-initialized at module load; self-resetting each launch)
__device__ unsigned g_best[NRAY];         // ~bits(min u); reset via atomicExch
__device__ int      g_done[BPOSE];        // chunk counter; reset by finalizer

__global__ __launch_bounds__(TPB)
void raycast_kernel(const float4* __restrict__ seg, const float* __restrict__ pose,
                    float* __restrict__ out)
{
    const int pz    = blockIdx.x >> 4;           // pose
    const int chunk = blockIdx.x & (SCH - 1);
    const int tid   = threadIdx.x;               // tid == beam
    const int lane  = tid & 31;

    __shared__ float4 s_pk[CHSEG];   // (sx, sy, dx, dy)
    __shared__ float  s_na[CHSEG];   // num_a
    __shared__ int    s_cnt;
    __shared__ int    s_last;

    if (tid == 0) s_cnt = 0;

    const float px = pose[pz * 3 + 0];
    const float py = pose[pz * 3 + 1];
    const float th = pose[pz * 3 + 2];
    __syncthreads();

    // ---- phase A: distance cull + compact into smem (1 segment per thread)
    {
        float4 q = seg[chunk * CHSEG + tid];
        float sx = q.z - q.x;
        float sy = q.w - q.y;
        float dx = px - q.x;      // AP = P - A
        float dy = py - q.y;

        // point-to-segment squared distance <= R2M, division-free
        float c    = dx * sx + dy * sy;          // dot(AP, S)
        float s2   = sx * sx + sy * sy;          // |S|^2
        float apsq = dx * dx + dy * dy;
        float bx = dx - sx, by = dy - sy;        // BP = P - B
        float bpsq = bx * bx + by * by;
        bool pass;
        if (c <= 0.0f)      pass = apsq <= R2M;
        else if (c >= s2)   pass = bpsq <= R2M;
        else                pass = (apsq * s2 - c * c) <= R2M * s2;

        unsigned m = __ballot_sync(0xffffffffu, pass);
        if (m) {
            int leader = __ffs(m) - 1;
            int base = 0;
            if (lane == leader) base = atomicAdd(&s_cnt, __popc(m));
            base = __shfl_sync(0xffffffffu, base, leader);
            if (pass) {
                int p = base + __popc(m & ((1u << lane) - 1u));
                s_pk[p] = make_float4(sx, sy, dx, dy);
                s_na[p] = sx * dy - sy * dx;     // num_a (reference formula)
            }
        }
    }
    __syncthreads();

    const float kstep = (float)(FOV_F / (double)L_OBS);
    const float ang = (float)tid * kstep + th;
    float rx, ry;
    sincosf(ang, &ry, &rx);                      // one range reduction

    // ---- phase B: exact test over the compacted list, dual accumulators
    // (even/odd entries tracked independently to break the loop-carried chain)
    float bn0 = CUDART_INF_F, ba0 = 1.0f;
    float bn1 = CUDART_INF_F, ba1 = 1.0f;
    const int m2 = s_cnt;

    int j = 0;
    #pragma unroll 4
    for (; j + 1 < m2; j += 2) {
        float4 p0  = s_pk[j];
        float  n0  = s_na[j];
        float4 p1  = s_pk[j + 1];
        float  n1  = s_na[j + 1];

        float nb0  = rx * p0.w - ry * p0.z;
        float rxs0 = p0.y * rx - p0.x * ry;
        float aa0  = fabsf(rxs0);
        float an0  = fabsf(n0);
        bool v0 = (aa0 >= EPS_PAR) & (nb0 * rxs0 >= 0.0f)
                & (fabsf(nb0) <= aa0) & (n0 * rxs0 >= 0.0f);
        if (v0 && (an0 * ba0 < bn0 * aa0)) { bn0 = an0; ba0 = aa0; }

        float nb1  = rx * p1.w - ry * p1.z;
        float rxs1 = p1.y * rx - p1.x * ry;
        float aa1  = fabsf(rxs1);
        float an1  = fabsf(n1);
        bool v1 = (aa1 >= EPS_PAR) & (nb1 * rxs1 >= 0.0f)
                & (fabsf(nb1) <= aa1) & (n1 * rxs1 >= 0.0f);
        if (v1 && (an1 * ba1 < bn1 * aa1)) { bn1 = an1; ba1 = aa1; }
    }
    if (j < m2) {
        float4 p0  = s_pk[j];
        float  n0  = s_na[j];
        float nb0  = rx * p0.w - ry * p0.z;
        float rxs0 = p0.y * rx - p0.x * ry;
        float aa0  = fabsf(rxs0);
        float an0  = fabsf(n0);
        bool v0 = (aa0 >= EPS_PAR) & (nb0 * rxs0 >= 0.0f)
                & (fabsf(nb0) <= aa0) & (n0 * rxs0 >= 0.0f);
        if (v0 && (an0 * ba0 < bn0 * aa0)) { bn0 = an0; ba0 = aa0; }
    }
    // merge the two chains
    if (bn1 * ba0 < bn0 * ba1) { bn0 = bn1; ba0 = ba1; }

    const int ray = pz * L_OBS + tid;
    float ublk = bn0 / ba0;                  // inf if nothing valid in chunk
    atomicMax(&g_best[ray], ~__float_as_uint(ublk));

    // ---- last chunk-block of this pose finalizes its 512 beams
    __syncthreads();
    if (tid == 0) {
        __threadfence();
        s_last = (atomicAdd(&g_done[pz], 1) == SCH - 1) ? 1 : 0;
    }
    __syncthreads();
    if (!s_last) return;
    __threadfence();

    unsigned key = atomicExch(&g_best[ray], 0u);   // read + reset for replay
    float u = __uint_as_float(~key);

    // Resolved iff u <= RCUT (any better segment would have dist <= u <= RCUT
    // and thus be in the culled set). Otherwise: exact full scan.
    bool unres = !(u <= RCUT);                     // catches inf and > RCUT
    if (__any_sync(0xffffffffu, unres)) {
        float bn = CUDART_INF_F, ba = 1.0f;
        for (int k = 0; k < NSEG; ++k) {
            float4 q = __ldg(&seg[k]);
            float sx = q.z - q.x;
            float sy = q.w - q.y;
            float dx = px - q.x;
            float dy = py - q.y;
            float nai = sx * dy - sy * dx;
            float nb  = rx * dy - ry * dx;
            float rxs = sy * rx - sx * ry;
            float absa  = fabsf(rxs);
            float absna = fabsf(nai);
            bool valid = (absa >= EPS_PAR) & (nb * rxs >= 0.0f)
                       & (fabsf(nb) <= absa) & (nai * rxs >= 0.0f);
            if (valid && (absna * ba < bn * absa)) { bn = absna; ba = absa; }
        }
        float uf = bn / ba;
        if (isinf(uf)) {
            // Reference: argmin over all-inf returns idx 0 -> u_a[0] (parallel -> 0)
            float4 q = __ldg(&seg[0]);
            float sx = q.z - q.x;
            float sy = q.w - q.y;
            float dx = px - q.x;
            float dy = py - q.y;
            float num_a = sx * dy - sy * dx;
            float rxs   = sy * rx - sx * ry;
            uf = (fabsf(rxs) < EPS_PAR) ? 0.0f : (num_a / rxs);
        }
        if (unres) u = uf;
    }

    const float ix = px + rx * u;
    const float iy = py + ry * u;

    const int gi = ray * 2;
    out[gi + 0] = ix;
    out[gi + 1] = iy;

    float s, c;
    sincosf(th, &s, &c);
    const float ddx = ix - px;
    const float ddy = iy - py;
    out[NRAY * 2 + gi + 0] =  ddx * c + ddy * s;
    out[NRAY * 2 + gi + 1] = -ddx * s + ddy * c;

    if (tid == 0) g_done[pz] = 0;            // reset for next launch/replay
}

extern "C" void kernel_launch(void* const* d_in, const int* in_sizes, int n_in,
                              void* d_out, int out_size)
{
    const float4* seg  = (const float4*)d_in[0];   // line_seg [8192, 4]
    const float*  pose = (const float*)d_in[1];    // pose [8, 3]
    float* out = (float*)d_out;

    raycast_kernel<<<BPOSE * SCH, TPB>>>(seg, pose, out);
}